// round 1
// baseline (speedup 1.0000x reference)
#include <cuda_runtime.h>
#include <cuda_bf16.h>

// Problem constants (fixed by setup_inputs): b=1, h=w=64, s=5, H=W=1024, ps=32, q=8
#define GRID_T   64
#define NTILES   (GRID_T * GRID_T)      // 4096
#define NSTROKE  5
#define IMG      1024
#define PLANE    (IMG * IMG)            // 1048576

// Scratch (allocation-free rule: __device__ globals)
__device__ int    g_cnt[NTILES];
__device__ float4 g_sA[NTILES * NSTROKE];   // (C, S, U0, V0)
__device__ float4 g_sB[NTILES * NSTROKE];   // (W, H, -, -)
__device__ float4 g_sC[NTILES * NSTROKE];   // (cr, cg, cb, -)

__device__ __forceinline__ float ex2_fast(float x) {
    float r; asm("ex2.approx.ftz.f32 %0, %1;" : "=f"(r) : "f"(x)); return r;
}
__device__ __forceinline__ float rcp_fast(float x) {
    float r; asm("rcp.approx.ftz.f32 %0, %1;" : "=f"(r) : "f"(x)); return r;
}

// ---------------------------------------------------------------------------
// Kernel 1: per-tile stroke preprocessing + dec==0 compaction.
// One thread per tile (4096 threads).
// ---------------------------------------------------------------------------
__global__ void prep_kernel(const float* __restrict__ param,
                            const int*   __restrict__ decision) {
    int t = blockIdx.x * blockDim.x + threadIdx.x;
    if (t >= NTILES) return;

    const float L = 72.13475204444817f;  // 50 * log2(e)
    int cnt = 0;
    #pragma unroll
    for (int i = 0; i < NSTROKE; i++) {
        int n = t * NSTROKE + i;
        if (decision[n] == 0) continue;      // alpha *= 0 -> identity blend, skip
        const float* q = param + (size_t)n * 12;
        float p[8];
        #pragma unroll
        for (int k = 0; k < 8; k++)
            p[k] = 1.0f / (1.0f + expf(-q[k]));     // jax.nn.sigmoid

        float x0 = p[0], y0 = p[1];
        float hw = fmaxf(p[2], 0.01f) * 0.5f;
        float hh = fmaxf(p[3], 0.01f) * 0.5f;
        float th = p[4] * 3.14159265358979323846f;
        float st, ct;
        sincosf(th, &st, &ct);

        // Fold 50*log2(e) and rotation into affine coefficients:
        //   L*u = gx*C + gy*S + U0 ;  L*v = gy*C - gx*S + V0
        //   e1 = 2^(|L*u| - L*hw)   ;  alpha = 1/((1+e1)(1+e2))
        float C  = L * ct, S = L * st;
        float U0 = -(x0 * C + y0 * S);
        float V0 =  (x0 * S - y0 * C);

        int o = t * NSTROKE + cnt;
        g_sA[o] = make_float4(C, S, U0, V0);
        g_sB[o] = make_float4(L * hw, L * hh, 0.f, 0.f);
        g_sC[o] = make_float4(p[5], p[6], p[7], 0.f);
        cnt++;
    }
    g_cnt[t] = cnt;
}

// ---------------------------------------------------------------------------
// Kernel 2: per-pixel blend. Tile (r,c) covers padded [16r,16r+32)x[16c,16c+32).
// Pass order: (even,even) -> (odd,odd) -> (odd,even) -> (even,odd).
// ---------------------------------------------------------------------------
__global__ void render_kernel(const float* __restrict__ canvas,
                              float*       __restrict__ out) {
    int x = blockIdx.x * blockDim.x + threadIdx.x;
    int y = blockIdx.y * blockDim.y + threadIdx.y;
    int X = x + 8;   // padded coords (q = 8)
    int Y = y + 8;

    int idx = y * IMG + x;
    float vr = canvas[idx];
    float vg = canvas[PLANE + idx];
    float vb = canvas[2 * PLANE + idx];

    int rh = Y >> 4, rl = rh - 1;     // candidate covering tile rows
    int chc = X >> 4, cl = chc - 1;   // candidate covering tile cols

    const int PR[4] = {0, 1, 1, 0};
    const int PC[4] = {0, 1, 0, 1};

    #pragma unroll
    for (int ps = 0; ps < 4; ps++) {
        int r = ((rl & 1) == PR[ps]) ? rl : rh;   // exactly one candidate has this parity
        int c = ((cl & 1) == PC[ps]) ? cl : chc;
        if ((unsigned)r > 63u || (unsigned)c > 63u) continue;

        int t = r * GRID_T + c;
        float gx = ((float)(X - 16 * c) + 0.5f) * 0.03125f;
        float gy = ((float)(Y - 16 * r) + 0.5f) * 0.03125f;

        int cnt = g_cnt[t];
        int base = t * NSTROKE;
        for (int i = 0; i < cnt; i++) {           // ORDER MATTERS: sequential blend
            float4 A  = g_sA[base + i];
            float4 B  = g_sB[base + i];
            float4 Cc = g_sC[base + i];

            float u  = fmaf(gx, A.x, fmaf(gy, A.y, A.z));
            float v  = fmaf(gy, A.x, fmaf(-gx, A.y, A.w));
            float e1 = ex2_fast(fabsf(u) - B.x);
            float e2 = ex2_fast(fabsf(v) - B.y);
            float alpha = rcp_fast((1.0f + e1) * (1.0f + e2));  // inf -> 0 (outside), 1 (inside)

            vr = fmaf(alpha, Cc.x - vr, vr);      // val = c*a + val*(1-a)
            vg = fmaf(alpha, Cc.y - vg, vg);
            vb = fmaf(alpha, Cc.z - vb, vb);
        }
    }

    out[idx]             = vr;
    out[PLANE + idx]     = vg;
    out[2 * PLANE + idx] = vb;
}

// ---------------------------------------------------------------------------
extern "C" void kernel_launch(void* const* d_in, const int* in_sizes, int n_in,
                              void* d_out, int out_size) {
    const float* param    = (const float*)d_in[0];   // (1,64,64,5,12) f32
    const int*   decision = (const int*)  d_in[1];   // (1,64,64,5)    i32
    const float* canvas   = (const float*)d_in[2];   // (1,3,1024,1024) f32
    float*       out      = (float*)d_out;           // (1,3,1024,1024) f32

    prep_kernel<<<(NTILES + 255) / 256, 256>>>(param, decision);

    dim3 bs(32, 8);
    dim3 gs(IMG / 32, IMG / 8);
    render_kernel<<<gs, bs>>>(canvas, out);
}

// round 2
// speedup vs baseline: 2.1313x; 2.1313x over previous
#include <cuda_runtime.h>
#include <cuda_bf16.h>

// Problem constants: b=1, h=w=64, s=5, H=W=1024, ps=32, q=8
#define GRID_T   64
#define NTILES   (GRID_T * GRID_T)      // 4096
#define NSTROKE  5
#define IMG      1024
#define PLANE    (IMG * IMG)            // 1048576

// Scratch (allocation-free rule: __device__ globals)
__device__ int    g_cnt[NTILES];
__device__ float4 g_sA[NTILES * NSTROKE];   // (C, S, U0, V0)
__device__ float4 g_sB[NTILES * NSTROKE];   // (W, H, -, -)
__device__ float4 g_sC[NTILES * NSTROKE];   // (cr, cg, cb, -)

__device__ __forceinline__ float ex2_fast(float x) {
    float r; asm("ex2.approx.ftz.f32 %0, %1;" : "=f"(r) : "f"(x)); return r;
}
__device__ __forceinline__ float rcp_fast(float x) {
    float r; asm("rcp.approx.ftz.f32 %0, %1;" : "=f"(r) : "f"(x)); return r;
}

// ---------------------------------------------------------------------------
// Kernel 1: per-STROKE preprocessing, order-preserving compaction of dec==1.
// One thread per stroke (20480 threads).
// ---------------------------------------------------------------------------
__global__ void prep_kernel(const float* __restrict__ param,
                            const int*   __restrict__ decision) {
    int n = blockIdx.x * blockDim.x + threadIdx.x;
    if (n >= NTILES * NSTROKE) return;
    int t = n / NSTROKE;
    int i = n - t * NSTROKE;

    // order-preserving compaction position + tile count
    int d[NSTROKE];
    #pragma unroll
    for (int j = 0; j < NSTROKE; j++) d[j] = decision[t * NSTROKE + j];
    if (i == 0) {
        int cnt = 0;
        #pragma unroll
        for (int j = 0; j < NSTROKE; j++) cnt += (d[j] != 0);
        g_cnt[t] = cnt;
    }
    if (d[i] == 0) return;
    int pos = 0;
    #pragma unroll
    for (int j = 0; j < NSTROKE; j++) pos += (j < i) && (d[j] != 0);

    const float L = 72.13475204444817f;  // 50 * log2(e)
    const float* q = param + (size_t)n * 12;
    float p[8];
    #pragma unroll
    for (int k = 0; k < 8; k++)
        p[k] = 1.0f / (1.0f + expf(-q[k]));     // jax.nn.sigmoid

    float x0 = p[0], y0 = p[1];
    float hw = fmaxf(p[2], 0.01f) * 0.5f;
    float hh = fmaxf(p[3], 0.01f) * 0.5f;
    float th = p[4] * 3.14159265358979323846f;
    float st, ct;
    sincosf(th, &st, &ct);

    // L*u = gx*C + gy*S + U0 ;  L*v = gy*C - gx*S + V0
    // e1 = 2^(|L*u| - L*hw)   ;  alpha = 1/((1+e1)(1+e2))
    float C  = L * ct, S = L * st;
    float U0 = -(x0 * C + y0 * S);
    float V0 =  (x0 * S - y0 * C);

    int o = t * NSTROKE + pos;
    g_sA[o] = make_float4(C, S, U0, V0);
    g_sB[o] = make_float4(L * hw, L * hh, 0.f, 0.f);
    g_sC[o] = make_float4(p[5], p[6], p[7], 0.f);
}

// ---------------------------------------------------------------------------
// Kernel 2: block = one 16x16 padded-aligned pixel cell. The 4 covering tiles
// (one per parity pass) are uniform across the block -> stage them in smem.
// 128 threads, 2 pixels each (rows ty and ty+8).
// Pass order: (even,even) -> (odd,odd) -> (odd,even) -> (even,odd).
// ---------------------------------------------------------------------------
__global__ void __launch_bounds__(128)
render_kernel(const float* __restrict__ canvas,
              float*       __restrict__ out) {
    __shared__ float4 sA[4][NSTROKE];
    __shared__ float4 sB[4][NSTROKE];
    __shared__ float4 sC[4][NSTROKE];
    __shared__ int    sCnt[4];
    __shared__ float  sOffX[4], sOffY[4];

    const int a = blockIdx.y;            // padded cell row: Y in [16a, 16a+16)
    const int b = blockIdx.x;            // padded cell col
    const int tx  = threadIdx.x;         // 0..15
    const int ty  = threadIdx.y;         // 0..7
    const int tid = ty * 16 + tx;

    const int PR[4] = {0, 1, 1, 0};
    const int PC[4] = {0, 1, 0, 1};

    // --- cooperative stage of up to 4 tiles' stroke constants ---
    if (tid < 4) {
        int p = tid;
        int r = (((a - 1) & 1) == PR[p]) ? (a - 1) : a;
        int c = (((b - 1) & 1) == PC[p]) ? (b - 1) : b;
        bool valid = ((unsigned)r < 64u) && ((unsigned)c < 64u);
        sCnt[p]  = valid ? g_cnt[r * GRID_T + c] : 0;
        sOffX[p] = ((float)(16 * b - 16 * c) + 0.5f) * 0.03125f;
        sOffY[p] = ((float)(16 * a - 16 * r) + 0.5f) * 0.03125f;
    }
    if (tid < 4 * NSTROKE) {
        int p = tid / NSTROKE, i = tid - p * NSTROKE;
        int r = (((a - 1) & 1) == PR[p]) ? (a - 1) : a;
        int c = (((b - 1) & 1) == PC[p]) ? (b - 1) : b;
        if (((unsigned)r < 64u) && ((unsigned)c < 64u)) {
            int o = (r * GRID_T + c) * NSTROKE + i;
            sA[p][i] = g_sA[o];
            sB[p][i] = g_sB[o];
            sC[p][i] = g_sC[o];
        }
    }
    __syncthreads();

    // --- two pixels per thread: (y0,x) and (y0+8,x), output coords ---
    const int x  = 16 * b + tx - 8;      // q = 8
    const int y0 = 16 * a + ty - 8;
    const int y1 = y0 + 8;
    const bool vx = (unsigned)x < (unsigned)IMG;
    const bool v0 = vx && ((unsigned)y0 < (unsigned)IMG);
    const bool v1 = vx && ((unsigned)y1 < (unsigned)IMG);

    const int i0 = y0 * IMG + x;
    const int i1 = y1 * IMG + x;

    float r0 = 0.f, g0 = 0.f, b0c = 0.f, r1 = 0.f, g1 = 0.f, b1c = 0.f;
    if (v0) { r0 = canvas[i0]; g0 = canvas[PLANE + i0]; b0c = canvas[2 * PLANE + i0]; }
    if (v1) { r1 = canvas[i1]; g1 = canvas[PLANE + i1]; b1c = canvas[2 * PLANE + i1]; }

    const float txf = (float)tx * 0.03125f;
    const float tyf = (float)ty * 0.03125f;

    #pragma unroll
    for (int p = 0; p < 4; p++) {
        const int   cnt = sCnt[p];
        const float gx  = txf + sOffX[p];
        const float gya = tyf + sOffY[p];
        const float gyb = gya + 0.25f;     // +8 px in tile-units (8/32)

        for (int i = 0; i < cnt; i++) {    // order matters: sequential blend
            float4 A = sA[p][i];
            float4 B = sB[p][i];
            float4 C = sC[p][i];

            float ua = fmaf(gx, A.x, fmaf(gya, A.y, A.z));
            float va = fmaf(gya, A.x, fmaf(-gx, A.y, A.w));
            float ub = fmaf(gx, A.x, fmaf(gyb, A.y, A.z));
            float vb = fmaf(gyb, A.x, fmaf(-gx, A.y, A.w));

            float e1a = ex2_fast(fabsf(ua) - B.x);
            float e2a = ex2_fast(fabsf(va) - B.y);
            float e1b = ex2_fast(fabsf(ub) - B.x);
            float e2b = ex2_fast(fabsf(vb) - B.y);

            float aa = rcp_fast((1.0f + e1a) * (1.0f + e2a));  // inf -> 0
            float ab = rcp_fast((1.0f + e1b) * (1.0f + e2b));

            r0  = fmaf(aa, C.x - r0,  r0);
            g0  = fmaf(aa, C.y - g0,  g0);
            b0c = fmaf(aa, C.z - b0c, b0c);
            r1  = fmaf(ab, C.x - r1,  r1);
            g1  = fmaf(ab, C.y - g1,  g1);
            b1c = fmaf(ab, C.z - b1c, b1c);
        }
    }

    if (v0) { out[i0] = r0; out[PLANE + i0] = g0; out[2 * PLANE + i0] = b0c; }
    if (v1) { out[i1] = r1; out[PLANE + i1] = g1; out[2 * PLANE + i1] = b1c; }
}

// ---------------------------------------------------------------------------
extern "C" void kernel_launch(void* const* d_in, const int* in_sizes, int n_in,
                              void* d_out, int out_size) {
    const float* param    = (const float*)d_in[0];   // (1,64,64,5,12) f32
    const int*   decision = (const int*)  d_in[1];   // (1,64,64,5)    i32
    const float* canvas   = (const float*)d_in[2];   // (1,3,1024,1024) f32
    float*       out      = (float*)d_out;           // (1,3,1024,1024) f32

    prep_kernel<<<(NTILES * NSTROKE + 255) / 256, 256>>>(param, decision);

    dim3 bs(16, 8);          // 128 threads, 2 px/thread
    dim3 gs(65, 65);         // padded 1040x1040 in 16x16 cells
    render_kernel<<<gs, bs>>>(canvas, out);
}